// round 13
// baseline (speedup 1.0000x reference)
#include <cuda_runtime.h>
#include <cuda_bf16.h>

// Problem shapes (fixed by reference setup_inputs)
#define B    4
#define CIN  512
#define OUT  256
#define NN   4096

// Quarter-row partial sums: X[row] = sum_q g_Xp[q][row].
// Fully overwritten every run -> no reset, no atomics, replay-safe.
__device__ float g_Xp[4][B * CIN];

// ---------------------------------------------------------------------------
// Kernel 1: 8192 blocks x 256 threads, ONE float4 load per thread.
// Block blk reduces quarter-row blk (4 KB): row = blk>>2, qtr = blk&3.
// Coverage: 8192 * 256 float4 = 2M float4 = 32 MB = all of x.  (R12 bug: half)
// MLP comes from raw thread count (2M threads, 1 un-serializable load each).
// ---------------------------------------------------------------------------
__global__ __launch_bounds__(256) void k_rowsum(const float* __restrict__ x) {
    const int blk = blockIdx.x;                 // 0..8191
    const int t   = threadIdx.x;

    // quarter-row base in float4 units: (blk>>2)*1024 + (blk&3)*256 = blk*256
    const float4 v =
        reinterpret_cast<const float4*>(x)[(size_t)blk * 256 + t];
    float s = (v.x + v.y) + (v.z + v.w);

    #pragma unroll
    for (int off = 16; off > 0; off >>= 1)
        s += __shfl_down_sync(0xffffffffu, s, off);

    __shared__ float sm[8];
    if ((t & 31) == 0) sm[t >> 5] = s;
    __syncthreads();
    if (t < 8) {
        float u = sm[t];
        #pragma unroll
        for (int off = 4; off > 0; off >>= 1)
            u += __shfl_down_sync(0xffu, u, off);
        if (t == 0) g_Xp[blk & 3][blk >> 2] = u;
    }
}

// ---------------------------------------------------------------------------
// Kernel 2: one output row per block (R7/R11-proven shape).
// Every warp redundantly computes the 512-dot, summing the 4 quarter-row
// partials per channel (all L1/L2-hot) -> no __syncthreads, 8 independent
// store streams per block.
// ---------------------------------------------------------------------------
__global__ __launch_bounds__(256) void k_out(const float* __restrict__ W1,
                                             float* __restrict__ out) {
    const int bo   = blockIdx.x;        // 0..1023
    const int b    = bo >> 8;           // OUT = 256
    const int o    = bo & 255;
    const int warp = threadIdx.x >> 5;  // 0..7
    const int lane = threadIdx.x & 31;

    const float4* __restrict__ wr =
        reinterpret_cast<const float4*>(W1) + (size_t)o * (CIN / 4);
    const float4* __restrict__ x0 =
        reinterpret_cast<const float4*>(&g_Xp[0][b * CIN]);
    const float4* __restrict__ x1 =
        reinterpret_cast<const float4*>(&g_Xp[1][b * CIN]);
    const float4* __restrict__ x2 =
        reinterpret_cast<const float4*>(&g_Xp[2][b * CIN]);
    const float4* __restrict__ x3 =
        reinterpret_cast<const float4*>(&g_Xp[3][b * CIN]);

    float s = 0.f;
    #pragma unroll
    for (int k = 0; k < 4; k++) {
        const int idx = lane + k * 32;
        const float4 a  = wr[idx];
        const float4 u0 = x0[idx];
        const float4 u1 = x1[idx];
        const float4 u2 = x2[idx];
        const float4 u3 = x3[idx];
        s = fmaf(a.x, (u0.x + u1.x) + (u2.x + u3.x),
            fmaf(a.y, (u0.y + u1.y) + (u2.y + u3.y),
            fmaf(a.z, (u0.z + u1.z) + (u2.z + u3.z),
            fmaf(a.w, (u0.w + u1.w) + (u2.w + u3.w), s))));
    }

    #pragma unroll
    for (int off = 16; off > 0; off >>= 1)     // butterfly: all lanes get sum
        s += __shfl_xor_sync(0xffffffffu, s, off);

    const float  e  = (s > 0.f) ? s : expm1f(s);   // elu, alpha=1
    const float4 v4 = make_float4(e, e, e, e);

    float4* __restrict__ q =
        reinterpret_cast<float4*>(out) + (size_t)bo * (NN / 4) + warp * 128;
    q[lane]      = v4;
    q[lane + 32] = v4;
    q[lane + 64] = v4;
    q[lane + 96] = v4;
}

extern "C" void kernel_launch(void* const* d_in, const int* in_sizes, int n_in,
                              void* d_out, int out_size) {
    const float* x  = (const float*)d_in[0];   // [B, CIN, 1, NN]
    const float* W1 = (const float*)d_in[1];   // [OUT, CIN]
    // d_in[2] = w2, d_in[3] = bias_mat: unused (softmax over size-1 axis == 1)
    float* out = (float*)d_out;                // [B, OUT, 1, NN]

    k_rowsum<<<4 * B * CIN, 256>>>(x);         // 8192 quarter-row blocks
    k_out  <<<B * OUT,      256>>>(W1, out);   // 1024 output-row blocks
}

// round 14
// speedup vs baseline: 1.5275x; 1.5275x over previous
#include <cuda_runtime.h>
#include <cuda_bf16.h>

// Problem shapes (fixed by reference setup_inputs)
#define B    4
#define CIN  512
#define OUT  256
#define NN   4096

// Scratch (no cudaMalloc allowed); fully overwritten every run
__device__ float g_X[B * CIN];   // X[b,c] = sum_n x[b,c,n]

// ---------------------------------------------------------------------------
// Kernel 1: reduce x over N. One block per (b,c) row (16 KB each).
// 256 threads x 4 front-batched float4. Triggers PDL completion at the end.
// (Best measured shape across 13 rounds: hot ~4.1us ≈ 7.8 TB/s L2 read rate.)
// ---------------------------------------------------------------------------
__global__ __launch_bounds__(256) void k_rowsum(const float* __restrict__ x) {
    const int row = blockIdx.x;                 // 0 .. B*CIN-1
    const float4* __restrict__ p =
        reinterpret_cast<const float4*>(x + (size_t)row * NN);
    const int t = threadIdx.x;

    float4 v0 = p[t];
    float4 v1 = p[t + 256];
    float4 v2 = p[t + 512];
    float4 v3 = p[t + 768];

    float s0 = (v0.x + v0.y) + (v0.z + v0.w);
    float s1 = (v1.x + v1.y) + (v1.z + v1.w);
    float s2 = (v2.x + v2.y) + (v2.z + v2.w);
    float s3 = (v3.x + v3.y) + (v3.z + v3.w);
    float s  = (s0 + s1) + (s2 + s3);

    #pragma unroll
    for (int off = 16; off > 0; off >>= 1)
        s += __shfl_down_sync(0xffffffffu, s, off);

    __shared__ float sm[8];
    if ((t & 31) == 0) sm[t >> 5] = s;
    __syncthreads();
    if (t < 8) {
        float u = sm[t];
        #pragma unroll
        for (int off = 4; off > 0; off >>= 1)
            u += __shfl_down_sync(0xffu, u, off);
        if (t == 0) g_X[row] = u;
    }

    // Allow the dependent kernel to start mounting / running its prologue.
    cudaTriggerProgrammaticLaunchCompletion();
}

// ---------------------------------------------------------------------------
// Kernel 2: 1024 blocks x 256 threads, one output row per block.
// Every warp REDUNDANTLY computes the row's 512-dot (L1/L2-hot, trivial cost)
// -> no __syncthreads, no shared memory, 8 fully independent store streams.
// PDL: W1 prologue runs before cudaGridDependencySynchronize().
// ---------------------------------------------------------------------------
__global__ __launch_bounds__(256) void k_out(const float* __restrict__ W1,
                                             float* __restrict__ out) {
    const int bo   = blockIdx.x;       // 0 .. 1023
    const int b    = bo >> 8;          // OUT = 256
    const int o    = bo & 255;
    const int warp = threadIdx.x >> 5; // 0..7
    const int lane = threadIdx.x & 31;

    // ---- prologue (independent of k_rowsum): load W1 row ----
    const float4* __restrict__ wr =
        reinterpret_cast<const float4*>(W1) + (size_t)o * (CIN / 4);
    float4 a0 = wr[lane];       float4 a1 = wr[lane + 32];
    float4 a2 = wr[lane + 64];  float4 a3 = wr[lane + 96];

    // ---- wait for k_rowsum's memory to be visible ----
    cudaGridDependencySynchronize();

    const float4* __restrict__ xr =
        reinterpret_cast<const float4*>(g_X) + (size_t)b * (CIN / 4);
    float4 b0 = xr[lane];       float4 b1 = xr[lane + 32];
    float4 b2 = xr[lane + 64];  float4 b3 = xr[lane + 96];

    float s0 = fmaf(a0.x, b0.x, fmaf(a0.y, b0.y, fmaf(a0.z, b0.z, a0.w * b0.w)));
    float s1 = fmaf(a1.x, b1.x, fmaf(a1.y, b1.y, fmaf(a1.z, b1.z, a1.w * b1.w)));
    float s2 = fmaf(a2.x, b2.x, fmaf(a2.y, b2.y, fmaf(a2.z, b2.z, a2.w * b2.w)));
    float s3 = fmaf(a3.x, b3.x, fmaf(a3.y, b3.y, fmaf(a3.z, b3.z, a3.w * b3.w)));
    float s  = (s0 + s1) + (s2 + s3);

    #pragma unroll
    for (int off = 16; off > 0; off >>= 1)     // butterfly: all lanes get sum
        s += __shfl_xor_sync(0xffffffffu, s, off);

    const float  e  = (s > 0.f) ? s : expm1f(s);   // elu, alpha=1
    const float4 v4 = make_float4(e, e, e, e);

    // warp owns float4 indices [warp*128, warp*128+128) of this 1024-f4 row
    float4* __restrict__ q =
        reinterpret_cast<float4*>(out) + (size_t)bo * (NN / 4) + warp * 128;
    q[lane]      = v4;
    q[lane + 32] = v4;
    q[lane + 64] = v4;
    q[lane + 96] = v4;
}

extern "C" void kernel_launch(void* const* d_in, const int* in_sizes, int n_in,
                              void* d_out, int out_size) {
    const float* x  = (const float*)d_in[0];   // [B, CIN, 1, NN]
    const float* W1 = (const float*)d_in[1];   // [OUT, CIN]
    // d_in[2] = w2, d_in[3] = bias_mat: unused (softmax over size-1 axis == 1)
    float* out = (float*)d_out;                // [B, OUT, 1, NN]

    k_rowsum<<<B * CIN, 256>>>(x);

    // Secondary launch with Programmatic Stream Serialization (PDL overlap).
    cudaLaunchConfig_t cfg = {};
    cfg.gridDim  = dim3(B * OUT, 1, 1);
    cfg.blockDim = dim3(256, 1, 1);
    cfg.dynamicSmemBytes = 0;
    cfg.stream = 0;
    cudaLaunchAttribute attr[1];
    attr[0].id = cudaLaunchAttributeProgrammaticStreamSerialization;
    attr[0].val.programmaticStreamSerializationAllowed = 1;
    cfg.attrs = attr;
    cfg.numAttrs = 1;
    cudaLaunchKernelEx(&cfg, k_out, W1, out);
}